// round 4
// baseline (speedup 1.0000x reference)
#include <cuda_runtime.h>
#include <mma.h>
#include <cstdint>

using namespace nvcuda;

#define N_NODES 50000
#define N_EDGES 800000
#define EDGE_DIM 16
#define EMB 128
#define HID 256

// ------------------------- scratch (static device arrays; no allocs) -------
__device__ float g_agg_n[(size_t)N_NODES * EMB];       // raw neighbor sums
__device__ float g_agg_e[(size_t)N_NODES * EDGE_DIM];
__device__ float g_deg[N_NODES];
__device__ float g_a_hi[(size_t)N_NODES * EMB];        // tf32 split of agg
__device__ float g_a_lo[(size_t)N_NODES * EMB];
__device__ float g_c1_hi[(size_t)N_NODES * HID];       // tf32 split of relu(mlp1)
__device__ float g_c1_lo[(size_t)N_NODES * HID];
__device__ float g_w1_hi[EMB * HID], g_w1_lo[EMB * HID];
__device__ float g_w2_hi[HID * EMB], g_w2_lo[HID * EMB];
__device__ float g_h[(size_t)N_NODES * EMB];
__device__ float g_sum[EMB];
__device__ float g_sumsq[EMB];
__device__ float g_scale[EMB];
__device__ float g_shift[EMB];

// ------------------------- helpers -----------------------------------------
__device__ __forceinline__ uint32_t smem_u32(const void* p) {
  uint32_t a;
  asm("{ .reg .u64 t; cvta.to.shared.u64 t, %1; cvt.u32.u64 %0, t; }" : "=r"(a) : "l"(p));
  return a;
}
__device__ __forceinline__ void cp16(uint32_t dst, const void* src) {
  asm volatile("cp.async.cg.shared.global [%0], [%1], 16;" :: "r"(dst), "l"(src));
}
__device__ __forceinline__ void cp16z(uint32_t dst, const void* src, uint32_t srcsz) {
  asm volatile("cp.async.cg.shared.global [%0], [%1], 16, %2;"
               :: "r"(dst), "l"(src), "r"(srcsz));
}
#define CP_COMMIT() asm volatile("cp.async.commit_group;" ::: "memory")
#define CP_WAIT1()  asm volatile("cp.async.wait_group 1;" ::: "memory")

__device__ __forceinline__ void split2(float x, float& hi, float& lo) {
  hi = wmma::__float_to_tf32(x);
  lo = wmma::__float_to_tf32(x - hi);
}

// ------------------------- zero scratch ------------------------------------
__global__ void zero_kernel() {
  int i = blockIdx.x * blockDim.x + threadIdx.x;
  int stride = gridDim.x * blockDim.x;
  const int T1 = N_NODES * EMB;
  const int T2 = T1 + N_NODES * EDGE_DIM;
  const int T3 = T2 + N_NODES;
  const int T4 = T3 + 2 * EMB;
  for (; i < T4; i += stride) {
    if (i < T1) g_agg_n[i] = 0.f;
    else if (i < T2) g_agg_e[i - T1] = 0.f;
    else if (i < T3) g_deg[i - T2] = 0.f;
    else if (i < T3 + EMB) g_sum[i - T3] = 0.f;
    else g_sumsq[i - T3 - EMB] = 0.f;
  }
}

// ------------------------- split weights ------------------------------------
__global__ void split_weights(const float* __restrict__ W1, const float* __restrict__ W2) {
  int i = blockIdx.x * blockDim.x + threadIdx.x;
  if (i < EMB * HID) {
    split2(W1[i], g_w1_hi[i], g_w1_lo[i]);
    split2(W2[i], g_w2_hi[i], g_w2_lo[i]);
  }
}

// ------------------------- edge scatter -------------------------------------
__device__ __forceinline__ void red4(float* p, float4 v) {
  asm volatile("red.global.add.v4.f32 [%0], {%1,%2,%3,%4};"
               :: "l"(p), "f"(v.x), "f"(v.y), "f"(v.z), "f"(v.w) : "memory");
}

__global__ void edge_kernel(const float* __restrict__ nf, const float* __restrict__ ef,
                            const int* __restrict__ src, const int* __restrict__ dst) {
  int e = (blockIdx.x * blockDim.x + threadIdx.x) >> 5;
  int lane = threadIdx.x & 31;
  if (e >= N_EDGES) return;
  int s = src[e], d = dst[e];
  float4 v = reinterpret_cast<const float4*>(nf)[s * (EMB / 4) + lane];
  red4(&g_agg_n[d * EMB + lane * 4], v);
  if (lane < EDGE_DIM / 4) {
    float4 ev = reinterpret_cast<const float4*>(ef)[e * (EDGE_DIM / 4) + lane];
    red4(&g_agg_e[d * EDGE_DIM + lane * 4], ev);
  }
  if (lane == 0) atomicAdd(&g_deg[d], 1.0f);
}

// agg = agg_n + agg_e @ W_edge + deg * b_edge ; split -> a_hi/a_lo
__global__ void combine_kernel(const float* __restrict__ W_edge,
                               const float* __restrict__ b_edge) {
  __shared__ float se[EDGE_DIM];
  __shared__ float sdeg;
  int n = blockIdx.x;
  int j = threadIdx.x;
  if (j < EDGE_DIM) se[j] = g_agg_e[n * EDGE_DIM + j];
  if (j == 0) sdeg = g_deg[n];
  __syncthreads();
  float acc = g_agg_n[n * EMB + j] + sdeg * b_edge[j];
#pragma unroll
  for (int i = 0; i < EDGE_DIM; i++)
    acc = fmaf(se[i], W_edge[i * EMB + j], acc);
  float hi, lo;
  split2(acc, hi, lo);
  g_a_hi[n * EMB + j] = hi;
  g_a_lo[n * EMB + j] = lo;
}

// ------------------------- pipelined wmma tf32 GEMM -------------------------
// C[M, N_] = (Ahi+Alo)[M, K_] @ (Whi+Wlo)[K_, N_] + bias (3-term split).
// CTA tile 128x128, BK=32, 2-stage cp.async double buffer, 8 warps of 32x64.
#define AS_STRIDE 40
#define BS_STRIDE 136
#define AS_HI_OFF 0
#define AS_LO_OFF (128 * AS_STRIDE)                     // 5120
#define BS_HI_OFF (2 * 128 * AS_STRIDE)                 // 10240
#define BS_LO_OFF (BS_HI_OFF + 32 * BS_STRIDE)          // 14592
#define STAGE_FLOATS (BS_LO_OFF + 32 * BS_STRIDE)       // 18944
#define GEMM_SMEM_BYTES (2 * STAGE_FLOATS * 4)          // 151552

template <int N_, int K_, bool FIRST>
__global__ __launch_bounds__(256, 1)
void wmma_gemm(const float* __restrict__ bias) {
  constexpr int M = N_NODES;
  constexpr int CH = K_ / 32;
  const float* __restrict__ Ahi = FIRST ? g_a_hi : g_c1_hi;
  const float* __restrict__ Alo = FIRST ? g_a_lo : g_c1_lo;
  const float* __restrict__ Whi = FIRST ? g_w1_hi : g_w2_hi;
  const float* __restrict__ Wlo = FIRST ? g_w1_lo : g_w2_lo;

  extern __shared__ __align__(16) float sm[];
  const uint32_t smb = smem_u32(sm);

  int tid = threadIdx.x;
  int wid = tid >> 5;
  int wm = wid & 3;
  int wn = wid >> 2;
  int bm = blockIdx.y * 128;
  int bn = blockIdx.x * 128;

  // ---- stage bias (replicated 16 rows) into stage0 B area; init acc ----
  for (int i = tid; i < 16 * 128; i += 256) {
    int r = i >> 7, c = i & 127;
    sm[BS_HI_OFF + r * BS_STRIDE + c] = bias[bn + c];
  }
  __syncthreads();
  wmma::fragment<wmma::accumulator, 16, 16, 8, float> acc[2][4];
#pragma unroll
  for (int nt = 0; nt < 4; nt++) {
    wmma::fragment<wmma::accumulator, 16, 16, 8, float> bf;
    wmma::load_matrix_sync(bf, &sm[BS_HI_OFF + wn * 64 + nt * 16], BS_STRIDE,
                           wmma::mem_row_major);
#pragma unroll
    for (int e = 0; e < bf.num_elements; e++) {
      acc[0][nt].x[e] = bf.x[e];
      acc[1][nt].x[e] = bf.x[e];
    }
  }
  __syncthreads();

  // ---- prefetch helper (16 cp.async per thread per chunk) ----
  auto prefetch = [&](int c, int s) {
    uint32_t base = smb + (uint32_t)s * (STAGE_FLOATS * 4);
    int k0 = c * 32;
#pragma unroll
    for (int l = 0; l < 4; l++) {
      int idx = tid + l * 256;            // 1024 float4 slots for A
      int row = idx >> 3;
      int c4 = (idx & 7) << 2;
      int gr = bm + row;
      uint32_t ok = (gr < M) ? 16u : 0u;
      size_t go = (size_t)gr * K_ + k0 + c4;
      uint32_t so = (uint32_t)(row * AS_STRIDE + c4) * 4;
      cp16z(base + AS_HI_OFF * 4 + so, &Ahi[go], ok);
      cp16z(base + AS_LO_OFF * 4 + so, &Alo[go], ok);
    }
#pragma unroll
    for (int l = 0; l < 4; l++) {
      int idx = tid + l * 256;            // 1024 float4 slots for B
      int row = idx >> 5;
      int c4 = (idx & 31) << 2;
      size_t go = (size_t)(k0 + row) * N_ + bn + c4;
      uint32_t so = (uint32_t)(row * BS_STRIDE + c4) * 4;
      cp16(base + BS_HI_OFF * 4 + so, &Whi[go]);
      cp16(base + BS_LO_OFF * 4 + so, &Wlo[go]);
    }
  };

  prefetch(0, 0); CP_COMMIT();
  if (CH > 1) prefetch(1, 1);
  CP_COMMIT();

  for (int c = 0; c < CH; c++) {
    CP_WAIT1();
    __syncthreads();
    const float* st = sm + (c & 1) * STAGE_FLOATS;
#pragma unroll
    for (int k8 = 0; k8 < 4; k8++) {
      wmma::fragment<wmma::matrix_a, 16, 16, 8, wmma::precision::tf32, wmma::row_major> ah[2], al[2];
#pragma unroll
      for (int mt = 0; mt < 2; mt++) {
        const float* ap = st + (wm * 32 + mt * 16) * AS_STRIDE + k8 * 8;
        wmma::load_matrix_sync(ah[mt], ap + AS_HI_OFF, AS_STRIDE);
        wmma::load_matrix_sync(al[mt], ap + AS_LO_OFF, AS_STRIDE);
      }
#pragma unroll
      for (int nt = 0; nt < 4; nt++) {
        wmma::fragment<wmma::matrix_b, 16, 16, 8, wmma::precision::tf32, wmma::row_major> bh, bl;
        const float* bp = st + (k8 * 8) * BS_STRIDE + wn * 64 + nt * 16;
        wmma::load_matrix_sync(bh, bp + BS_HI_OFF, BS_STRIDE);
        wmma::load_matrix_sync(bl, bp + BS_LO_OFF, BS_STRIDE);
#pragma unroll
        for (int mt = 0; mt < 2; mt++) {
          wmma::mma_sync(acc[mt][nt], ah[mt], bh, acc[mt][nt]);
          wmma::mma_sync(acc[mt][nt], al[mt], bh, acc[mt][nt]);
          wmma::mma_sync(acc[mt][nt], ah[mt], bl, acc[mt][nt]);
        }
      }
    }
    __syncthreads();
    if (c + 2 < CH) prefetch(c + 2, c & 1);
    CP_COMMIT();
  }

  // ---- epilogue ----
#pragma unroll
  for (int nt = 0; nt < 4; nt++) {
#pragma unroll
    for (int mt = 0; mt < 2; mt++) {
      int row0 = bm + wm * 32 + mt * 16;     // M % 16 == 0: frag valid iff row0 < M
      if (row0 >= M) continue;
      if (FIRST) {
        wmma::fragment<wmma::accumulator, 16, 16, 8, float> fh, fl;
#pragma unroll
        for (int e = 0; e < fh.num_elements; e++) {
          float v = fmaxf(acc[mt][nt].x[e], 0.f);
          float hi, lo;
          split2(v, hi, lo);
          fh.x[e] = hi;
          fl.x[e] = lo;
        }
        size_t off = (size_t)row0 * N_ + bn + wn * 64 + nt * 16;
        wmma::store_matrix_sync(&g_c1_hi[off], fh, N_, wmma::mem_row_major);
        wmma::store_matrix_sync(&g_c1_lo[off], fl, N_, wmma::mem_row_major);
      } else {
        size_t off = (size_t)row0 * N_ + bn + wn * 64 + nt * 16;
        wmma::store_matrix_sync(&g_h[off], acc[mt][nt], N_, wmma::mem_row_major);
      }
    }
  }
}

// ------------------------- BN stats over g_h --------------------------------
__global__ void bn_stats() {
  __shared__ float4 ssum[8][32];
  __shared__ float4 ssq[8][32];
  int tid = threadIdx.x;
  int r0 = tid >> 5;
  int cq = tid & 31;
  int base = blockIdx.x * 128;
  float4 s = make_float4(0.f, 0.f, 0.f, 0.f);
  float4 q = make_float4(0.f, 0.f, 0.f, 0.f);
#pragma unroll
  for (int step = 0; step < 16; step++) {
    int row = base + r0 + step * 8;
    if (row < N_NODES) {
      float4 h = reinterpret_cast<const float4*>(g_h)[row * 32 + cq];
      s.x += h.x; s.y += h.y; s.z += h.z; s.w += h.w;
      q.x += h.x * h.x; q.y += h.y * h.y; q.z += h.z * h.z; q.w += h.w * h.w;
    }
  }
  ssum[r0][cq] = s;
  ssq[r0][cq] = q;
  __syncthreads();
  if (tid < 32) {
    float4 ts = ssum[0][tid], tq = ssq[0][tid];
#pragma unroll
    for (int r = 1; r < 8; r++) {
      float4 a = ssum[r][tid], b2 = ssq[r][tid];
      ts.x += a.x; ts.y += a.y; ts.z += a.z; ts.w += a.w;
      tq.x += b2.x; tq.y += b2.y; tq.z += b2.z; tq.w += b2.w;
    }
    atomicAdd(&g_sum[tid * 4 + 0], ts.x); atomicAdd(&g_sum[tid * 4 + 1], ts.y);
    atomicAdd(&g_sum[tid * 4 + 2], ts.z); atomicAdd(&g_sum[tid * 4 + 3], ts.w);
    atomicAdd(&g_sumsq[tid * 4 + 0], tq.x); atomicAdd(&g_sumsq[tid * 4 + 1], tq.y);
    atomicAdd(&g_sumsq[tid * 4 + 2], tq.z); atomicAdd(&g_sumsq[tid * 4 + 3], tq.w);
  }
}

__global__ void bn_finalize(const float* __restrict__ gamma, const float* __restrict__ beta) {
  int n = threadIdx.x;
  const float invM = 1.0f / (float)N_NODES;
  float mean = g_sum[n] * invM;
  float var = g_sumsq[n] * invM - mean * mean;
  float sc = gamma[n] * rsqrtf(var + 1e-5f);
  g_scale[n] = sc;
  g_shift[n] = beta[n] - mean * sc;
}

__global__ void bn_apply(float* __restrict__ out) {
  int i = blockIdx.x * blockDim.x + threadIdx.x;
  const int total4 = N_NODES * EMB / 4;
  if (i >= total4) return;
  int c = (i & 31) << 2;
  float4 h = reinterpret_cast<const float4*>(g_h)[i];
  float4 o;
  o.x = h.x * g_scale[c + 0] + g_shift[c + 0];
  o.y = h.y * g_scale[c + 1] + g_shift[c + 1];
  o.z = h.z * g_scale[c + 2] + g_shift[c + 2];
  o.w = h.w * g_scale[c + 3] + g_shift[c + 3];
  reinterpret_cast<float4*>(out)[i] = o;
}

// ------------------------- launch -------------------------------------------
extern "C" void kernel_launch(void* const* d_in, const int* in_sizes, int n_in,
                              void* d_out, int out_size) {
  const float* node_feats = (const float*)d_in[0];
  const float* edge_feats = (const float*)d_in[1];
  const float* W_edge     = (const float*)d_in[2];
  const float* b_edge     = (const float*)d_in[3];
  const float* W1         = (const float*)d_in[4];
  const float* b1         = (const float*)d_in[5];
  const float* W2         = (const float*)d_in[6];
  const float* b2         = (const float*)d_in[7];
  const float* bn_gamma   = (const float*)d_in[8];
  const float* bn_beta    = (const float*)d_in[9];
  const int*   src        = (const int*)d_in[10];
  const int*   dst        = (const int*)d_in[11];
  float* out = (float*)d_out;

  cudaFuncSetAttribute(wmma_gemm<HID, EMB, true>,
                       cudaFuncAttributeMaxDynamicSharedMemorySize, GEMM_SMEM_BYTES);
  cudaFuncSetAttribute(wmma_gemm<EMB, HID, false>,
                       cudaFuncAttributeMaxDynamicSharedMemorySize, GEMM_SMEM_BYTES);

  const int MTILES = (N_NODES + 127) / 128;  // 391

  zero_kernel<<<2048, 256>>>();
  split_weights<<<(EMB * HID + 255) / 256, 256>>>(W1, W2);
  edge_kernel<<<(N_EDGES + 7) / 8, 256>>>(node_feats, edge_feats, src, dst);
  combine_kernel<<<N_NODES, EMB>>>(W_edge, b_edge);
  dim3 g1(HID / 128, MTILES);
  wmma_gemm<HID, EMB, true><<<g1, 256, GEMM_SMEM_BYTES>>>(b1);
  dim3 g2(EMB / 128, MTILES);
  wmma_gemm<EMB, HID, false><<<g2, 256, GEMM_SMEM_BYTES>>>(b2);
  bn_stats<<<MTILES, 256>>>();
  bn_finalize<<<1, EMB>>>(bn_gamma, bn_beta);
  bn_apply<<<(N_NODES * EMB / 4 + 255) / 256, 256>>>(out);
}

// round 7
// speedup vs baseline: 1.3704x; 1.3704x over previous
#include <cuda_runtime.h>
#include <cuda_bf16.h>
#include <mma.h>
#include <cstdint>

using namespace nvcuda;

#define N_NODES 50000
#define N_EDGES 800000
#define EDGE_DIM 16
#define EMB 128
#define HID 256

typedef __nv_bfloat16 bf16;
typedef __nv_bfloat162 bf162;

// ------------------------- scratch (static device arrays; no allocs) -------
__device__ float g_agg_n[(size_t)N_NODES * EMB];       // fp32 neighbor sums (red target)
__device__ float g_agg_e[(size_t)N_NODES * EDGE_DIM];
__device__ float g_deg[N_NODES];
__device__ bf16  g_a_hi[(size_t)N_NODES * EMB];        // bf16 split of agg
__device__ bf16  g_a_lo[(size_t)N_NODES * EMB];
__device__ bf16  g_c1_hi[(size_t)N_NODES * HID];       // bf16 split of relu(mlp1)
__device__ bf16  g_c1_lo[(size_t)N_NODES * HID];
__device__ bf16  g_w1_hi[EMB * HID], g_w1_lo[EMB * HID];
__device__ bf16  g_w2_hi[HID * EMB], g_w2_lo[HID * EMB];
__device__ float g_h[(size_t)N_NODES * EMB];
__device__ float g_sum[EMB];
__device__ float g_sumsq[EMB];
__device__ float g_scale[EMB];
__device__ float g_shift[EMB];

// ------------------------- helpers -----------------------------------------
__device__ __forceinline__ uint32_t smem_u32(const void* p) {
  uint32_t a;
  asm("{ .reg .u64 t; cvta.to.shared.u64 t, %1; cvt.u32.u64 %0, t; }" : "=r"(a) : "l"(p));
  return a;
}
__device__ __forceinline__ void cp16(uint32_t dst, const void* src) {
  asm volatile("cp.async.cg.shared.global [%0], [%1], 16;" :: "r"(dst), "l"(src));
}
__device__ __forceinline__ void cp16z(uint32_t dst, const void* src, uint32_t srcsz) {
  asm volatile("cp.async.cg.shared.global [%0], [%1], 16, %2;"
               :: "r"(dst), "l"(src), "r"(srcsz));
}
#define CP_COMMIT() asm volatile("cp.async.commit_group;" ::: "memory")
#define CP_WAIT1()  asm volatile("cp.async.wait_group 1;" ::: "memory")

__device__ __forceinline__ void splitbf(float x, bf16& hi, bf16& lo) {
  hi = __float2bfloat16(x);
  lo = __float2bfloat16(x - __bfloat162float(hi));
}

// ------------------------- zero scratch ------------------------------------
__global__ void zero_kernel() {
  int i = blockIdx.x * blockDim.x + threadIdx.x;
  int stride = gridDim.x * blockDim.x;
  const int T1 = N_NODES * EMB;
  const int T2 = T1 + N_NODES * EDGE_DIM;
  const int T3 = T2 + N_NODES;
  const int T4 = T3 + 2 * EMB;
  for (; i < T4; i += stride) {
    if (i < T1) g_agg_n[i] = 0.f;
    else if (i < T2) g_agg_e[i - T1] = 0.f;
    else if (i < T3) g_deg[i - T2] = 0.f;
    else if (i < T3 + EMB) g_sum[i - T3] = 0.f;
    else g_sumsq[i - T3 - EMB] = 0.f;
  }
}

// ------------------------- split weights ------------------------------------
__global__ void split_weights(const float* __restrict__ W1, const float* __restrict__ W2) {
  int i = blockIdx.x * blockDim.x + threadIdx.x;
  if (i < EMB * HID) {
    splitbf(W1[i], g_w1_hi[i], g_w1_lo[i]);
    splitbf(W2[i], g_w2_hi[i], g_w2_lo[i]);
  }
}

// ------------------------- edge scatter -------------------------------------
__device__ __forceinline__ void red4(float* p, float4 v) {
  asm volatile("red.global.add.v4.f32 [%0], {%1,%2,%3,%4};"
               :: "l"(p), "f"(v.x), "f"(v.y), "f"(v.z), "f"(v.w) : "memory");
}

__global__ void edge_kernel(const float* __restrict__ nf, const float* __restrict__ ef,
                            const int* __restrict__ src, const int* __restrict__ dst) {
  int e = (blockIdx.x * blockDim.x + threadIdx.x) >> 5;
  int lane = threadIdx.x & 31;
  if (e >= N_EDGES) return;
  int s = src[e], d = dst[e];
  float4 v = reinterpret_cast<const float4*>(nf)[s * (EMB / 4) + lane];
  red4(&g_agg_n[d * EMB + lane * 4], v);
  if (lane < EDGE_DIM / 4) {
    float4 ev = reinterpret_cast<const float4*>(ef)[e * (EDGE_DIM / 4) + lane];
    red4(&g_agg_e[d * EDGE_DIM + lane * 4], ev);
  }
  if (lane == 0) atomicAdd(&g_deg[d], 1.0f);
}

// agg = agg_n + agg_e @ W_edge + deg * b_edge -> bf16 hi/lo planes
// warp-per-node, W_edge cached in smem.
__global__ __launch_bounds__(256)
void combine_kernel(const float* __restrict__ W_edge, const float* __restrict__ b_edge) {
  __shared__ float sW[EDGE_DIM][EMB];
  __shared__ float sbe[EMB];
  int tid = threadIdx.x;
  for (int i = tid; i < EDGE_DIM * EMB; i += 256) sW[i >> 7][i & 127] = W_edge[i];
  if (tid < EMB) sbe[tid] = b_edge[tid];
  __syncthreads();

  int w = tid >> 5, lane = tid & 31;
  int n = blockIdx.x * 8 + w;
  if (n >= N_NODES) return;
  int c4 = lane * 4;
  float4 acc = *reinterpret_cast<const float4*>(&g_agg_n[(size_t)n * EMB + c4]);
  float deg = g_deg[n];
  float ev = (lane < EDGE_DIM) ? g_agg_e[n * EDGE_DIM + lane] : 0.f;
  acc.x += deg * sbe[c4 + 0];
  acc.y += deg * sbe[c4 + 1];
  acc.z += deg * sbe[c4 + 2];
  acc.w += deg * sbe[c4 + 3];
#pragma unroll
  for (int i = 0; i < EDGE_DIM; i++) {
    float s = __shfl_sync(0xffffffffu, ev, i);
    acc.x = fmaf(s, sW[i][c4 + 0], acc.x);
    acc.y = fmaf(s, sW[i][c4 + 1], acc.y);
    acc.z = fmaf(s, sW[i][c4 + 2], acc.z);
    acc.w = fmaf(s, sW[i][c4 + 3], acc.w);
  }
  bf162 h0, h1, l0, l1;
  splitbf(acc.x, h0.x, l0.x); splitbf(acc.y, h0.y, l0.y);
  splitbf(acc.z, h1.x, l1.x); splitbf(acc.w, h1.y, l1.y);
  size_t off = (size_t)n * EMB + c4;
  *reinterpret_cast<bf162*>(&g_a_hi[off]) = h0;
  *reinterpret_cast<bf162*>(&g_a_hi[off + 2]) = h1;
  *reinterpret_cast<bf162*>(&g_a_lo[off]) = l0;
  *reinterpret_cast<bf162*>(&g_a_lo[off + 2]) = l1;
}

// ------------------------- pipelined bf16 wmma GEMM -------------------------
// C[M, N_] = (Ahi+Alo)@(Whi+Wlo) + bias (3-product bf16 split).
// CTA tile 128x128, BK=32, 2-stage cp.async, 8 warps of 32x64.
#define A_STRIDE 48                       // bf16 elems per A smem row (96B, 16B-mult)
#define B_STRIDE 144                      // bf16 elems per B smem row (288B)
#define A_HI_OFF 0
#define A_LO_OFF (128 * A_STRIDE)         // 6144
#define B_HI_OFF (2 * 128 * A_STRIDE)     // 12288
#define B_LO_OFF (B_HI_OFF + 32 * B_STRIDE)
#define STAGE_ELEMS (B_LO_OFF + 32 * B_STRIDE)        // 21504 bf16
#define STAGE_BYTES (STAGE_ELEMS * 2)                 // 43008
#define GEMM_SMEM_BYTES (2 * STAGE_BYTES)             // 86016
#define EPI_STRIDE 132                                // f32 epilogue tile stride

template <int N_, int K_, bool FIRST>
__global__ __launch_bounds__(256, 2)
void wmma_gemm(const float* __restrict__ bias) {
  constexpr int M = N_NODES;
  constexpr int CH = K_ / 32;
  const bf16* __restrict__ Ahi = FIRST ? g_a_hi : g_c1_hi;
  const bf16* __restrict__ Alo = FIRST ? g_a_lo : g_c1_lo;
  const bf16* __restrict__ Whi = FIRST ? g_w1_hi : g_w2_hi;
  const bf16* __restrict__ Wlo = FIRST ? g_w1_lo : g_w2_lo;

  extern __shared__ __align__(16) bf16 smb[];
  float* smf = reinterpret_cast<float*>(smb);
  __shared__ float sbias[128];
  const uint32_t smb_b = smem_u32(smb);

  int tid = threadIdx.x;
  int wid = tid >> 5;
  int wm = wid & 3;
  int wn = wid >> 2;
  int bm = blockIdx.y * 128;
  int bn = blockIdx.x * 128;

  if (tid < 128) sbias[tid] = bias[bn + tid];

  wmma::fragment<wmma::accumulator, 16, 16, 16, float> acc[2][4];
#pragma unroll
  for (int mt = 0; mt < 2; mt++)
#pragma unroll
    for (int nt = 0; nt < 4; nt++) wmma::fill_fragment(acc[mt][nt], 0.f);

  auto prefetch = [&](int c, int s) {
    uint32_t base = smb_b + (uint32_t)s * STAGE_BYTES;
    int k0 = c * 32;
#pragma unroll
    for (int l = 0; l < 2; l++) {
      int u = tid + l * 256;              // 512 16B-units per plane
      // A planes: row = u>>2 (128 rows), seg = u&3 (8 bf16 each)
      int ar = u >> 2, as = u & 3;
      int gr = bm + ar;
      uint32_t ok = (gr < M) ? 16u : 0u;
      size_t ago = (size_t)gr * K_ + k0 + as * 8;
      uint32_t aso = (uint32_t)(ar * A_STRIDE + as * 8) * 2;
      cp16z(base + A_HI_OFF * 2 + aso, &Ahi[ago], ok);
      cp16z(base + A_LO_OFF * 2 + aso, &Alo[ago], ok);
      // B planes: row = u>>4 (32 rows), seg = u&15
      int br = u >> 4, bs = u & 15;
      size_t bgo = (size_t)(k0 + br) * N_ + bn + bs * 8;
      uint32_t bso = (uint32_t)(br * B_STRIDE + bs * 8) * 2;
      cp16(base + B_HI_OFF * 2 + bso, &Whi[bgo]);
      cp16(base + B_LO_OFF * 2 + bso, &Wlo[bgo]);
    }
  };

  prefetch(0, 0); CP_COMMIT();
  prefetch(1, 1); CP_COMMIT();

  for (int c = 0; c < CH; c++) {
    CP_WAIT1();
    __syncthreads();
    const bf16* st = smb + (c & 1) * STAGE_ELEMS;
#pragma unroll
    for (int ks = 0; ks < 2; ks++) {
      wmma::fragment<wmma::matrix_a, 16, 16, 16, bf16, wmma::row_major> ah[2], al[2];
#pragma unroll
      for (int mt = 0; mt < 2; mt++) {
        const bf16* ap = st + (wm * 32 + mt * 16) * A_STRIDE + ks * 16;
        wmma::load_matrix_sync(ah[mt], ap + A_HI_OFF, A_STRIDE);
        wmma::load_matrix_sync(al[mt], ap + A_LO_OFF, A_STRIDE);
      }
#pragma unroll
      for (int nt = 0; nt < 4; nt++) {
        wmma::fragment<wmma::matrix_b, 16, 16, 16, bf16, wmma::row_major> bh, bl;
        const bf16* bp = st + (ks * 16) * B_STRIDE + wn * 64 + nt * 16;
        wmma::load_matrix_sync(bh, bp + B_HI_OFF, B_STRIDE);
        wmma::load_matrix_sync(bl, bp + B_LO_OFF, B_STRIDE);
#pragma unroll
        for (int mt = 0; mt < 2; mt++) {
          wmma::mma_sync(acc[mt][nt], ah[mt], bh, acc[mt][nt]);
          wmma::mma_sync(acc[mt][nt], al[mt], bh, acc[mt][nt]);
          wmma::mma_sync(acc[mt][nt], ah[mt], bl, acc[mt][nt]);
        }
      }
    }
    __syncthreads();
    if (c + 2 < CH) prefetch(c + 2, c & 1);
    CP_COMMIT();
  }

  // ---- epilogue: fragments -> smem f32 tile -> bias/relu/split/store -------
#pragma unroll
  for (int mt = 0; mt < 2; mt++)
#pragma unroll
    for (int nt = 0; nt < 4; nt++)
      wmma::store_matrix_sync(&smf[(wm * 32 + mt * 16) * EPI_STRIDE + wn * 64 + nt * 16],
                              acc[mt][nt], EPI_STRIDE, wmma::mem_row_major);
  __syncthreads();

  {
    int r = tid >> 1;
    int c0 = (tid & 1) * 64;
    int gr = bm + r;
    if (gr < M) {
#pragma unroll
      for (int j = 0; j < 64; j += 4) {
        float4 v = *reinterpret_cast<float4*>(&smf[r * EPI_STRIDE + c0 + j]);
        v.x += sbias[c0 + j + 0]; v.y += sbias[c0 + j + 1];
        v.z += sbias[c0 + j + 2]; v.w += sbias[c0 + j + 3];
        if (FIRST) {
          v.x = fmaxf(v.x, 0.f); v.y = fmaxf(v.y, 0.f);
          v.z = fmaxf(v.z, 0.f); v.w = fmaxf(v.w, 0.f);
          bf162 h0, h1, l0, l1;
          splitbf(v.x, h0.x, l0.x); splitbf(v.y, h0.y, l0.y);
          splitbf(v.z, h1.x, l1.x); splitbf(v.w, h1.y, l1.y);
          size_t off = (size_t)gr * N_ + bn + c0 + j;
          *reinterpret_cast<bf162*>(&g_c1_hi[off]) = h0;
          *reinterpret_cast<bf162*>(&g_c1_hi[off + 2]) = h1;
          *reinterpret_cast<bf162*>(&g_c1_lo[off]) = l0;
          *reinterpret_cast<bf162*>(&g_c1_lo[off + 2]) = l1;
        } else {
          *reinterpret_cast<float4*>(&g_h[(size_t)gr * N_ + bn + c0 + j]) = v;
        }
      }
    }
  }

  if (!FIRST) {
    // fused BN stats: column-wise over the smem tile (h = smf + bias)
    __syncthreads();
    int c = tid & 127;
    int seg = tid >> 7;
    float b = sbias[c];
    float s = 0.f, q = 0.f;
#pragma unroll
    for (int rr = 0; rr < 64; rr++) {
      int gr = bm + seg * 64 + rr;
      if (gr < M) {
        float v = smf[(seg * 64 + rr) * EPI_STRIDE + c] + b;
        s += v; q += v * v;
      }
    }
    atomicAdd(&g_sum[c], s);
    atomicAdd(&g_sumsq[c], q);
  }
}

// ------------------------- BN finalize / apply ------------------------------
__global__ void bn_finalize(const float* __restrict__ gamma, const float* __restrict__ beta) {
  int n = threadIdx.x;
  const float invM = 1.0f / (float)N_NODES;
  float mean = g_sum[n] * invM;
  float var = g_sumsq[n] * invM - mean * mean;
  float sc = gamma[n] * rsqrtf(var + 1e-5f);
  g_scale[n] = sc;
  g_shift[n] = beta[n] - mean * sc;
}

__global__ void bn_apply(float* __restrict__ out) {
  int i = blockIdx.x * blockDim.x + threadIdx.x;
  const int total4 = N_NODES * EMB / 4;
  if (i >= total4) return;
  int c = (i & 31) << 2;
  float4 h = reinterpret_cast<const float4*>(g_h)[i];
  float4 o;
  o.x = h.x * g_scale[c + 0] + g_shift[c + 0];
  o.y = h.y * g_scale[c + 1] + g_shift[c + 1];
  o.z = h.z * g_scale[c + 2] + g_shift[c + 2];
  o.w = h.w * g_scale[c + 3] + g_shift[c + 3];
  reinterpret_cast<float4*>(out)[i] = o;
}

// ------------------------- launch -------------------------------------------
extern "C" void kernel_launch(void* const* d_in, const int* in_sizes, int n_in,
                              void* d_out, int out_size) {
  const float* node_feats = (const float*)d_in[0];
  const float* edge_feats = (const float*)d_in[1];
  const float* W_edge     = (const float*)d_in[2];
  const float* b_edge     = (const float*)d_in[3];
  const float* W1         = (const float*)d_in[4];
  const float* b1         = (const float*)d_in[5];
  const float* W2         = (const float*)d_in[6];
  const float* b2         = (const float*)d_in[7];
  const float* bn_gamma   = (const float*)d_in[8];
  const float* bn_beta    = (const float*)d_in[9];
  const int*   src        = (const int*)d_in[10];
  const int*   dst        = (const int*)d_in[11];
  float* out = (float*)d_out;

  cudaFuncSetAttribute(wmma_gemm<HID, EMB, true>,
                       cudaFuncAttributeMaxDynamicSharedMemorySize, GEMM_SMEM_BYTES);
  cudaFuncSetAttribute(wmma_gemm<EMB, HID, false>,
                       cudaFuncAttributeMaxDynamicSharedMemorySize, GEMM_SMEM_BYTES);

  const int MTILES = (N_NODES + 127) / 128;  // 391

  zero_kernel<<<2048, 256>>>();
  split_weights<<<(EMB * HID + 255) / 256, 256>>>(W1, W2);
  edge_kernel<<<(N_EDGES + 7) / 8, 256>>>(node_feats, edge_feats, src, dst);
  combine_kernel<<<(N_NODES + 7) / 8, 256>>>(W_edge, b_edge);
  dim3 g1(HID / 128, MTILES);
  wmma_gemm<HID, EMB, true><<<g1, 256, GEMM_SMEM_BYTES>>>(b1);
  dim3 g2(EMB / 128, MTILES);
  wmma_gemm<EMB, HID, false><<<g2, 256, GEMM_SMEM_BYTES>>>(b2);
  bn_finalize<<<1, EMB>>>(bn_gamma, bn_beta);
  bn_apply<<<(N_NODES * EMB / 4 + 255) / 256, 256>>>(out);
}